// round 14
// baseline (speedup 1.0000x reference)
#include <cuda_runtime.h>
#include <cuda_bf16.h>
#include <cstdint>
#include <math.h>

// ---------------- problem constants ----------------
#define D_MODEL   1024
#define NUM_TILES 64
#define TPC       8
#define NUM_CL    8
#define COMP_H    256
#define GRIDW     16
#define EPS_LN    1e-5f

// ---------------- GEMM config ----------------
#define NCOL      336              // 42 n8-tiles: 256 hidden + 8 cluster + 64 tile + 8 pad
#define NCOL_PAD  384              // g_Wcat row count (prep writes all; k1 reads 336)
#define M_BLK     64
#define KC        64
#define NCHUNK    (D_MODEL / KC)   // 16
#define ROWB      144              // 128B k-data + 16B pad; ldmatrix conflict-free
#define NTHREADS  512

#define A_BYTES      (M_BLK * ROWB)           // 9216
#define B_BYTES      (NCOL * ROWB)            // 48384
#define STAGE_BYTES  (A_BYTES + B_BYTES)      // 57600
#define B_SEGS       (NCOL * 8)               // 2688 16B-segs per chunk
#define SMEM_TOTAL   (2 * STAGE_BYTES)        // 115200

// Wcat, chunk-major: [chunk][row n][k within chunk]
__device__ __nv_bfloat16 g_Wcat[NCHUNK][NCOL_PAD][KC];
// C scores buffer [N tokens][NCOL]
__device__ float g_C[16384 * NCOL];

// ---------------- merged prep: W1 transpose + signatures + pad --------------
__global__ void prep_kernel(const float* __restrict__ w1,
                            const float* __restrict__ raw) {
    __shared__ float t[32][33];
    const int b = blockIdx.x;
    if (b < 256) {
        const int tx = threadIdx.x & 31, ty = threadIdx.x >> 5;   // 32 x 8
        const int n0 = (b & 7) * 32, k0 = (b >> 3) * 32;
        #pragma unroll
        for (int r = 0; r < 4; ++r) {
            int k = k0 + ty + r * 8;
            t[ty + r * 8][tx] = w1[(size_t)k * COMP_H + n0 + tx];
        }
        __syncthreads();
        #pragma unroll
        for (int r = 0; r < 4; ++r) {
            int n = n0 + ty + r * 8;
            int k = k0 + tx;
            g_Wcat[k >> 6][n][k & 63] = __float2bfloat16(t[tx][ty + r * 8]);
        }
    } else {
        const int nn = b - 256;          // 0..127 -> n = 256..383
        const int n = COMP_H + nn;
        #pragma unroll
        for (int r = 0; r < 4; ++r) {
            int k = threadIdx.x + r * 256;
            float val;
            if (nn < NUM_CL) {
                float s = 0.f;
                #pragma unroll
                for (int j = 0; j < TPC; ++j) {
                    float rv = raw[(size_t)(nn * TPC + j) * D_MODEL + k];
                    s += (rv > 0.3f) ? 1.f : ((rv < -0.3f) ? -1.f : 0.f);
                }
                val = (s > 0.f) ? 1.f : ((s < 0.f) ? -1.f : 0.f);
            } else if (nn < NUM_CL + NUM_TILES) {
                float rv = raw[(size_t)(nn - NUM_CL) * D_MODEL + k];
                val = (rv > 0.3f) ? 1.f : ((rv < -0.3f) ? -1.f : 0.f);
            } else {
                val = 0.f;
            }
            g_Wcat[k >> 6][n][k & 63] = __float2bfloat16(val);
        }
    }
}

// ---------------- helpers ----------------
__device__ __forceinline__ float gelu_exact(float v) {
    return 0.5f * v * (1.0f + erff(v * 0.7071067811865476f));
}
__device__ __forceinline__ void mma16816(float c[4], uint32_t a0, uint32_t a1,
                                         uint32_t a2, uint32_t a3,
                                         uint32_t b0, uint32_t b1) {
    asm volatile(
        "mma.sync.aligned.m16n8k16.row.col.f32.bf16.bf16.f32 "
        "{%0,%1,%2,%3}, {%4,%5,%6,%7}, {%8,%9}, {%0,%1,%2,%3};\n"
        : "+f"(c[0]), "+f"(c[1]), "+f"(c[2]), "+f"(c[3])
        : "r"(a0), "r"(a1), "r"(a2), "r"(a3), "r"(b0), "r"(b1));
}
__device__ __forceinline__ void ldsm_x4(uint32_t& r0, uint32_t& r1, uint32_t& r2,
                                        uint32_t& r3, uint32_t addr) {
    asm volatile("ldmatrix.sync.aligned.m8n8.x4.shared.b16 {%0,%1,%2,%3}, [%4];"
                 : "=r"(r0), "=r"(r1), "=r"(r2), "=r"(r3) : "r"(addr));
}
__device__ __forceinline__ void cp16(uint32_t dst, const void* src) {
    asm volatile("cp.async.ca.shared.global [%0], [%1], 16;\n" :: "r"(dst), "l"(src));
}
__device__ __forceinline__ void warp_argmax(float& v, int& i) {
    #pragma unroll
    for (int o = 16; o; o >>= 1) {
        float ov = __shfl_xor_sync(0xffffffffu, v, o);
        int   oi = __shfl_xor_sync(0xffffffffu, i, o);
        if (ov > v || (ov == v && oi < i)) { v = ov; i = oi; }
    }
}
__device__ __forceinline__ float warp_sum(float v) {
    #pragma unroll
    for (int o = 16; o; o >>= 1) v += __shfl_xor_sync(0xffffffffu, v, o);
    return v;
}
__device__ __forceinline__ uint32_t as_u32(__nv_bfloat162 h) {
    return *reinterpret_cast<uint32_t*>(&h);
}

// ---------------- K1: GEMM -> g_C ----------------
__global__ void __launch_bounds__(NTHREADS)
gemm_kernel(const float* __restrict__ X) {
    extern __shared__ char sm[];
    const uint32_t smem_u32 = (uint32_t)__cvta_generic_to_shared(sm);

    const int tid  = threadIdx.x;
    const int lane = tid & 31;
    const int wid  = tid >> 5;      // 0..15
    const int mw   = wid & 1;       // 2 m-groups of 32 rows
    const int nw   = wid >> 1;      // 0..7; nw<7 compute (7 groups x 48 cols)
    const bool compute = (wid < 14);
    const int r0   = blockIdx.x * M_BLK;

    float acc[2][6][4];
    #pragma unroll
    for (int mt = 0; mt < 2; ++mt)
        #pragma unroll
        for (int nt = 0; nt < 6; ++nt)
            #pragma unroll
            for (int j = 0; j < 4; ++j) acc[mt][nt][j] = 0.f;

    const float4* X4 = (const float4*)X;
    const int arow = tid >> 3, asg = tid & 7;      // A-fill: 512 segs of 16B

    const uint32_t a_lm0 = (uint32_t)((mw * 32 + (lane & 15)) * ROWB + (lane >> 4) * 16);
    const uint32_t a_lm1 = a_lm0 + 16u * ROWB;
    const uint32_t b_lm4 = (uint32_t)((((lane >> 4) & 1) * 8 + (lane & 7)) * ROWB
                                      + ((lane >> 3) & 1) * 16);

    auto fill_B = [&](int kc, int stage) {
        const char* src = (const char*)&g_Wcat[kc][0][0];
        uint32_t bb = smem_u32 + stage * STAGE_BYTES + A_BYTES;
        #pragma unroll
        for (int rep = 0; rep < 6; ++rep) {
            int s = tid + rep * NTHREADS;
            if (s < B_SEGS)
                cp16(bb + (s >> 3) * ROWB + (s & 7) * 16, src + s * 16);
        }
        asm volatile("cp.async.commit_group;\n");
    };
    auto store_A = [&](const float4& v0, const float4& v1, int stage) {
        uint4 hh = make_uint4(as_u32(__floats2bfloat162_rn(v0.x, v0.y)),
                              as_u32(__floats2bfloat162_rn(v0.z, v0.w)),
                              as_u32(__floats2bfloat162_rn(v1.x, v1.y)),
                              as_u32(__floats2bfloat162_rn(v1.z, v1.w)));
        *(uint4*)(sm + stage * STAGE_BYTES + arow * ROWB + asg * 16) = hh;
    };

    // ---- prologue: stage 0 <- chunk 0 ----
    {
        fill_B(0, 0);
        const float4* p = X4 + (size_t)(r0 + arow) * (D_MODEL / 4) + asg * 2;
        float4 v0 = p[0], v1 = p[1];
        store_A(v0, v1, 0);
        asm volatile("cp.async.wait_group 0;\n");
        __syncthreads();
    }

    // ---- pipelined mainloop ----
    for (int kc = 0; kc < NCHUNK; ++kc) {
        const int cur = kc & 1, nxt = cur ^ 1;
        const bool has_next = (kc + 1 < NCHUNK);
        const uint32_t sb = smem_u32 + cur * STAGE_BYTES;

        float4 v0, v1;
        if (has_next) {
            const float4* p = X4 + (size_t)(r0 + arow) * (D_MODEL / 4)
                              + (kc + 1) * (KC / 4) + asg * 2;
            v0 = p[0]; v1 = p[1];
            fill_B(kc + 1, nxt);
        }

        if (compute) {
            #pragma unroll
            for (int ks = 0; ks < 4; ++ks) {
                uint32_t a0[4], a1[4];
                ldsm_x4(a0[0], a0[1], a0[2], a0[3], sb + a_lm0 + ks * 32);
                ldsm_x4(a1[0], a1[1], a1[2], a1[3], sb + a_lm1 + ks * 32);
                const uint32_t bbase = sb + A_BYTES + (uint32_t)(nw * 48 * ROWB) + ks * 32;
                uint32_t p0, p1, p2, p3;
                ldsm_x4(p0, p1, p2, p3, bbase + b_lm4);
                #pragma unroll
                for (int p = 0; p < 3; ++p) {
                    uint32_t q0, q1, q2, q3;
                    if (p < 2)
                        ldsm_x4(q0, q1, q2, q3, bbase + b_lm4 + (uint32_t)((p + 1) * 16 * ROWB));
                    mma16816(acc[0][2 * p],     a0[0], a0[1], a0[2], a0[3], p0, p1);
                    mma16816(acc[1][2 * p],     a1[0], a1[1], a1[2], a1[3], p0, p1);
                    mma16816(acc[0][2 * p + 1], a0[0], a0[1], a0[2], a0[3], p2, p3);
                    mma16816(acc[1][2 * p + 1], a1[0], a1[1], a1[2], a1[3], p2, p3);
                    p0 = q0; p1 = q1; p2 = q2; p3 = q3;
                }
            }
        }

        if (has_next) store_A(v0, v1, nxt);
        asm volatile("cp.async.wait_group 0;\n");
        __syncthreads();
    }

    // ---- store C directly from accumulators (32B-sector aligned float2) ----
    if (compute) {
        #pragma unroll
        for (int mt = 0; mt < 2; ++mt)
            #pragma unroll
            for (int nt = 0; nt < 6; ++nt) {
                int rr = r0 + mw * 32 + mt * 16 + (lane >> 2);
                int cc = (nw * 6 + nt) * 8 + (lane & 3) * 2;
                *(float2*)&g_C[(size_t)rr * NCOL + cc] =
                    make_float2(acc[mt][nt][0], acc[mt][nt][1]);
                *(float2*)&g_C[(size_t)(rr + 8) * NCOL + cc] =
                    make_float2(acc[mt][nt][2], acc[mt][nt][3]);
            }
    }
}

// ---------------- K2: per-token epilogue, one 256-thread block per token ----
__global__ void __launch_bounds__(256)
epi_kernel(const float* __restrict__ X,
           const float* __restrict__ cb1,
           const float* __restrict__ cw2,
           const float* __restrict__ cb2,
           const float* __restrict__ sw1,
           const float* __restrict__ sb1,
           const float* __restrict__ sw2,
           const float* __restrict__ sb2,
           const float* __restrict__ dirs,
           const float* __restrict__ gamma,
           const float* __restrict__ beta,
           const float* __restrict__ oscale_p,
           float* __restrict__ out) {
    __shared__ float sred[2][8];
    __shared__ float sbr[4];       // factor, tile, mu, rstd

    const int r    = blockIdx.x;
    const int tid  = threadIdx.x;
    const int lane = tid & 31;
    const int wid  = tid >> 5;
    const float* crow = g_C + (size_t)r * NCOL;

    // compress head: gelu(C[:256] + b1) dot w2 (block reduce)
    {
        float c = crow[tid];
        float h = gelu_exact(c + cb1[tid]);
        float s0 = h * cw2[tid * 2 + 0];
        float s1 = h * cw2[tid * 2 + 1];
        s0 = warp_sum(s0);
        s1 = warp_sum(s1);
        if (lane == 0) { sred[0][wid] = s0; sred[1][wid] = s1; }
    }
    __syncthreads();

    // warp 0: finish reductions, routing, spline -> factor, tile
    if (wid == 0) {
        float s0 = (lane < 8) ? sred[0][lane] : 0.f;
        float s1 = (lane < 8) ? sred[1][lane] : 0.f;
        s0 = warp_sum(s0);
        s1 = warp_sum(s1);
        float comp0 = tanhf(s0 + cb2[0]);
        float comp1 = tanhf(s1 + cb2[1]);

        // routing (calibration monotone -> argmax of raw scores)
        float cv = -INFINITY; int ci = 1 << 20;
        if (lane < NUM_CL) { cv = crow[COMP_H + lane]; ci = lane; }
        warp_argmax(cv, ci);
        float tv = -INFINITY; int tl = 1 << 20;
        if (lane < TPC) { tv = crow[COMP_H + NUM_CL + ci * TPC + lane]; tl = lane; }
        warp_argmax(tv, tl);
        const int tile = ci * TPC + tl;

        // tiny spline MLP
        float contrib = 0.f;
        if (lane < GRIDW) {
            int g = lane;
            float hw = comp0 * sw1[tile * 32 + g] + comp1 * sw1[tile * 32 + 16 + g]
                       + sb1[tile * 16 + g];
            hw = fmaxf(hw, 0.f);
            contrib = hw * sw2[tile * 16 + g];
        }
        float mag = warp_sum(contrib) + sb2[tile];
        if (lane == 0) {
            sbr[0] = mag * oscale_p[0];
            sbr[1] = __int_as_float(tile);
        }
    }
    __syncthreads();

    const float factor = sbr[0];
    const int   tile   = __float_as_int(sbr[1]);

    // residual + layernorm: thread tid handles float4 #tid of the row
    const float4 xv = ((const float4*)(X + (size_t)r * D_MODEL))[tid];
    const float4 dv = ((const float4*)(dirs + (size_t)tile * D_MODEL))[tid];
    float4 y;
    y.x = xv.x + factor * dv.x;
    y.y = xv.y + factor * dv.y;
    y.z = xv.z + factor * dv.z;
    y.w = xv.w + factor * dv.w;
    float sum   = y.x + y.y + y.z + y.w;
    float sumsq = y.x * y.x + y.y * y.y + y.z * y.z + y.w * y.w;
    sum   = warp_sum(sum);
    sumsq = warp_sum(sumsq);
    __syncthreads();   // sred reuse
    if (lane == 0) { sred[0][wid] = sum; sred[1][wid] = sumsq; }
    __syncthreads();
    if (wid == 0) {
        float ts  = (lane < 8) ? sred[0][lane] : 0.f;
        float tss = (lane < 8) ? sred[1][lane] : 0.f;
        ts  = warp_sum(ts);
        tss = warp_sum(tss);
        if (lane == 0) {
            float mu  = ts * (1.f / D_MODEL);
            float var = tss * (1.f / D_MODEL) - mu * mu;
            sbr[2] = mu;
            sbr[3] = rsqrtf(var + EPS_LN);
        }
    }
    __syncthreads();
    const float mu = sbr[2], rstd = sbr[3];
    const float4 gv = ((const float4*)gamma)[tid];
    const float4 bv = ((const float4*)beta)[tid];
    float4 o;
    o.x = (y.x - mu) * rstd * gv.x + bv.x;
    o.y = (y.y - mu) * rstd * gv.y + bv.y;
    o.z = (y.z - mu) * rstd * gv.z + bv.z;
    o.w = (y.w - mu) * rstd * gv.w + bv.w;
    ((float4*)(out + (size_t)r * D_MODEL))[tid] = o;
}

// ---------------- launch ----------------
extern "C" void kernel_launch(void* const* d_in, const int* in_sizes, int n_in,
                              void* d_out, int out_size) {
    const float* x      = (const float*)d_in[0];
    const float* sraw   = (const float*)d_in[1];
    // d_in[2] knot_values, d_in[3] temperature: unused (calibration monotone)
    const float* cw1    = (const float*)d_in[4];
    const float* cb1    = (const float*)d_in[5];
    const float* cw2    = (const float*)d_in[6];
    const float* cb2    = (const float*)d_in[7];
    const float* sw1    = (const float*)d_in[8];
    const float* sb1    = (const float*)d_in[9];
    const float* sw2    = (const float*)d_in[10];
    const float* sb2    = (const float*)d_in[11];
    const float* dirs   = (const float*)d_in[12];
    const float* gamma  = (const float*)d_in[13];
    const float* beta   = (const float*)d_in[14];
    const float* oscale = (const float*)d_in[15];
    float* out = (float*)d_out;

    const int N = in_sizes[0] / D_MODEL;     // 16384
    const int nblocks = N / M_BLK;           // 256

    cudaFuncSetAttribute(gemm_kernel,
                         cudaFuncAttributeMaxDynamicSharedMemorySize, SMEM_TOTAL);

    prep_kernel<<<384, 256>>>(cw1, sraw);
    gemm_kernel<<<nblocks, NTHREADS, SMEM_TOTAL>>>(x);
    epi_kernel<<<N, 256>>>(x, cb1, cw2, cb2, sw1, sb1, sw2, sb2,
                           dirs, gamma, beta, oscale, out);
}

// round 15
// speedup vs baseline: 1.3086x; 1.3086x over previous
#include <cuda_runtime.h>
#include <cuda_bf16.h>
#include <cstdint>
#include <math.h>

// ---------------- problem constants ----------------
#define D_MODEL   1024
#define NUM_TILES 64
#define TPC       8
#define NUM_CL    8
#define COMP_H    256
#define GRIDW     16
#define EPS_LN    1e-5f

// ---------------- GEMM config ----------------
#define NCOL_PAD  384              // 48 n8-tiles (256 hidden + 8 cluster + 64 tile + 56 pad)
#define M_BLK     64
#define KC        64
#define NCHUNK    (D_MODEL / KC)   // 16
#define ROWB      144              // 128B k-data + 16B pad; ldmatrix conflict-free
#define CSTRIDE   388              // float4-aligned rows, 4-bank row shift
#define NTHREADS  512

#define A_BYTES      (M_BLK * ROWB)           // 9216
#define B_BYTES      (NCOL_PAD * ROWB)        // 55296
#define STAGE_BYTES  (A_BYTES + B_BYTES)      // 64512
#define B_SEGS       (NCOL_PAD * 8)           // 3072 16B-segs per chunk
#define PARAM_OFF    (2 * STAGE_BYTES)        // 129024 (Csm 99328 aliases stages)
#define SMEM_TOTAL   (PARAM_OFF + 3 * COMP_H * 4)   // 132096

// Wcat, chunk-major: [chunk][row n][k within chunk]
__device__ __nv_bfloat16 g_Wcat[NCHUNK][NCOL_PAD][KC];

// ---------------- merged prep: W1 transpose + signatures + pad --------------
__global__ void prep_kernel(const float* __restrict__ w1,
                            const float* __restrict__ raw) {
    __shared__ float t[32][33];
    const int b = blockIdx.x;
    if (b < 256) {
        const int tx = threadIdx.x & 31, ty = threadIdx.x >> 5;   // 32 x 8
        const int n0 = (b & 7) * 32, k0 = (b >> 3) * 32;
        #pragma unroll
        for (int r = 0; r < 4; ++r) {
            int k = k0 + ty + r * 8;
            t[ty + r * 8][tx] = w1[(size_t)k * COMP_H + n0 + tx];
        }
        __syncthreads();
        #pragma unroll
        for (int r = 0; r < 4; ++r) {
            int n = n0 + ty + r * 8;
            int k = k0 + tx;
            g_Wcat[k >> 6][n][k & 63] = __float2bfloat16(t[tx][ty + r * 8]);
        }
    } else {
        const int nn = b - 256;          // 0..127 -> n = 256..383
        const int n = COMP_H + nn;
        #pragma unroll
        for (int r = 0; r < 4; ++r) {
            int k = threadIdx.x + r * 256;
            float val;
            if (nn < NUM_CL) {
                float s = 0.f;
                #pragma unroll
                for (int j = 0; j < TPC; ++j) {
                    float rv = raw[(size_t)(nn * TPC + j) * D_MODEL + k];
                    s += (rv > 0.3f) ? 1.f : ((rv < -0.3f) ? -1.f : 0.f);
                }
                val = (s > 0.f) ? 1.f : ((s < 0.f) ? -1.f : 0.f);
            } else if (nn < NUM_CL + NUM_TILES) {
                float rv = raw[(size_t)(nn - NUM_CL) * D_MODEL + k];
                val = (rv > 0.3f) ? 1.f : ((rv < -0.3f) ? -1.f : 0.f);
            } else {
                val = 0.f;
            }
            g_Wcat[k >> 6][n][k & 63] = __float2bfloat16(val);
        }
    }
}

// ---------------- helpers ----------------
__device__ __forceinline__ float gelu_exact(float v) {
    return 0.5f * v * (1.0f + erff(v * 0.7071067811865476f));
}
__device__ __forceinline__ void mma16816(float c[4], const uint32_t a[4],
                                         uint32_t b0, uint32_t b1) {
    asm volatile(
        "mma.sync.aligned.m16n8k16.row.col.f32.bf16.bf16.f32 "
        "{%0,%1,%2,%3}, {%4,%5,%6,%7}, {%8,%9}, {%0,%1,%2,%3};\n"
        : "+f"(c[0]), "+f"(c[1]), "+f"(c[2]), "+f"(c[3])
        : "r"(a[0]), "r"(a[1]), "r"(a[2]), "r"(a[3]), "r"(b0), "r"(b1));
}
__device__ __forceinline__ void ldsm_x4(uint32_t* r, uint32_t addr) {
    asm volatile("ldmatrix.sync.aligned.m8n8.x4.shared.b16 {%0,%1,%2,%3}, [%4];"
                 : "=r"(r[0]), "=r"(r[1]), "=r"(r[2]), "=r"(r[3]) : "r"(addr));
}
__device__ __forceinline__ void cp16(uint32_t dst, const void* src) {
    asm volatile("cp.async.ca.shared.global [%0], [%1], 16;\n" :: "r"(dst), "l"(src));
}
__device__ __forceinline__ void warp_argmax(float& v, int& i) {
    #pragma unroll
    for (int o = 16; o; o >>= 1) {
        float ov = __shfl_xor_sync(0xffffffffu, v, o);
        int   oi = __shfl_xor_sync(0xffffffffu, i, o);
        if (ov > v || (ov == v && oi < i)) { v = ov; i = oi; }
    }
}
__device__ __forceinline__ float warp_sum(float v) {
    #pragma unroll
    for (int o = 16; o; o >>= 1) v += __shfl_xor_sync(0xffffffffu, v, o);
    return v;
}
__device__ __forceinline__ uint32_t as_u32(__nv_bfloat162 h) {
    return *reinterpret_cast<uint32_t*>(&h);
}

// ---------------- main fused kernel ----------------
__global__ void __launch_bounds__(NTHREADS)
fused_kernel(const float* __restrict__ X,
             const float* __restrict__ cb1,
             const float* __restrict__ cw2,
             const float* __restrict__ cb2,
             const float* __restrict__ sw1,
             const float* __restrict__ sb1,
             const float* __restrict__ sw2,
             const float* __restrict__ sb2,
             const float* __restrict__ dirs,
             const float* __restrict__ gamma,
             const float* __restrict__ beta,
             const float* __restrict__ oscale_p,
             float* __restrict__ out) {
    extern __shared__ char sm[];
    float* Csm  = (float*)sm;
    float* b1c  = (float*)(sm + PARAM_OFF);
    float* w2c0 = b1c + COMP_H;
    float* w2c1 = w2c0 + COMP_H;
    const uint32_t smem_u32 = (uint32_t)__cvta_generic_to_shared(sm);

    const int tid  = threadIdx.x;
    const int lane = tid & 31;
    const int wid  = tid >> 5;      // 0..15
    const int mw   = wid & 1;       // 2 m-groups of 32 rows
    const int nw   = wid >> 1;      // 8 n-groups of 48 cols (6 n8-tiles)
    const int r0   = blockIdx.x * M_BLK;

    if (tid < COMP_H) {
        b1c[tid]  = cb1[tid];
        w2c0[tid] = cw2[tid * 2 + 0];
        w2c1[tid] = cw2[tid * 2 + 1];
    }
    const float oscale = oscale_p[0];
    const float b2_0 = cb2[0];
    const float b2_1 = cb2[1];

    float acc[2][6][4];
    #pragma unroll
    for (int mt = 0; mt < 2; ++mt)
        #pragma unroll
        for (int nt = 0; nt < 6; ++nt)
            #pragma unroll
            for (int j = 0; j < 4; ++j) acc[mt][nt][j] = 0.f;

    const float4* X4 = (const float4*)X;
    const int arow = tid >> 3, asg = tid & 7;      // A-fill: 512 segs of 16B

    // per-warp ldmatrix offsets (within a stage)
    const uint32_t a_lm0 = (uint32_t)((mw * 32 + (lane & 15)) * ROWB + (lane >> 4) * 16);
    const uint32_t a_lm1 = a_lm0 + 16u * ROWB;
    const uint32_t b_lm4 = (uint32_t)((((lane >> 4) & 1) * 8 + (lane & 7)) * ROWB
                                      + ((lane >> 3) & 1) * 16);

    auto fill_B = [&](int kc, int stage) {
        const char* src = (const char*)&g_Wcat[kc][0][0];
        uint32_t bb = smem_u32 + stage * STAGE_BYTES + A_BYTES;
        #pragma unroll
        for (int rep = 0; rep < 6; ++rep) {
            int s = tid + rep * NTHREADS;        // exactly B_SEGS = 3072
            cp16(bb + (s >> 3) * ROWB + (s & 7) * 16, src + s * 16);
        }
        asm volatile("cp.async.commit_group;\n");
    };
    auto store_A = [&](const float4& v0, const float4& v1, int stage) {
        uint4 hh = make_uint4(as_u32(__floats2bfloat162_rn(v0.x, v0.y)),
                              as_u32(__floats2bfloat162_rn(v0.z, v0.w)),
                              as_u32(__floats2bfloat162_rn(v1.x, v1.y)),
                              as_u32(__floats2bfloat162_rn(v1.z, v1.w)));
        *(uint4*)(sm + stage * STAGE_BYTES + arow * ROWB + asg * 16) = hh;
    };

    // ---- prologue: stage 0 <- chunk 0 ----
    {
        fill_B(0, 0);
        const float4* p = X4 + (size_t)(r0 + arow) * (D_MODEL / 4) + asg * 2;
        float4 v0 = p[0], v1 = p[1];
        store_A(v0, v1, 0);
        asm volatile("cp.async.wait_group 0;\n");
        __syncthreads();
    }

    // ---- pipelined mainloop ----
    for (int kc = 0; kc < NCHUNK; ++kc) {
        const int cur = kc & 1, nxt = cur ^ 1;
        const bool has_next = (kc + 1 < NCHUNK);
        const uint32_t sb = smem_u32 + cur * STAGE_BYTES;

        float4 v0, v1;
        if (has_next) {
            const float4* p = X4 + (size_t)(r0 + arow) * (D_MODEL / 4)
                              + (kc + 1) * (KC / 4) + asg * 2;
            v0 = p[0]; v1 = p[1];
            fill_B(kc + 1, nxt);
        }

        // MMA block: flat 12-pair stream, LDSM pipelined across k-step bounds
        {
            const uint32_t bb0 = sb + A_BYTES + (uint32_t)(nw * 48 * ROWB);
            uint32_t A0[4], A1[4], B[2][4];
            ldsm_x4(A0, sb + a_lm0);
            ldsm_x4(A1, sb + a_lm1);
            ldsm_x4(B[0], bb0 + b_lm4);          // pair j=0
            #pragma unroll
            for (int j = 0; j < 12; ++j) {
                const int ks = j / 3, p = j % 3;
                const int curb = j & 1;
                if (j < 11) {
                    const int jn = j + 1;
                    ldsm_x4(B[curb ^ 1],
                            bb0 + (uint32_t)((jn / 3) * 32)
                                + (uint32_t)((jn % 3) * 16 * ROWB) + b_lm4);
                }
                mma16816(acc[0][2 * p],     A0, B[curb][0], B[curb][1]);
                mma16816(acc[1][2 * p],     A1, B[curb][0], B[curb][1]);
                mma16816(acc[0][2 * p + 1], A0, B[curb][2], B[curb][3]);
                mma16816(acc[1][2 * p + 1], A1, B[curb][2], B[curb][3]);
                if (p == 2 && ks < 3) {      // reload A for next k-step (WAR, no new regs)
                    ldsm_x4(A0, sb + a_lm0 + (ks + 1) * 32);
                    ldsm_x4(A1, sb + a_lm1 + (ks + 1) * 32);
                }
            }
        }

        if (has_next) store_A(v0, v1, nxt);
        asm volatile("cp.async.wait_group 0;\n");
        __syncthreads();
    }

    // ---- dump C to smem (stages dead now) ----
    #pragma unroll
    for (int mt = 0; mt < 2; ++mt)
        #pragma unroll
        for (int nt = 0; nt < 6; ++nt) {
            int cr = mw * 32 + mt * 16 + (lane >> 2);
            int cc = (nw * 6 + nt) * 8 + (lane & 3) * 2;
            *(float2*)&Csm[cr * CSTRIDE + cc] =
                make_float2(acc[mt][nt][0], acc[mt][nt][1]);
            *(float2*)&Csm[(cr + 8) * CSTRIDE + cc] =
                make_float2(acc[mt][nt][2], acc[mt][nt][3]);
        }
    __syncthreads();

    // ---- epilogue: one warp per token, 4 tokens per warp ----
    for (int it = 0; it < 4; ++it) {
        const int m = wid * 4 + it;
        const int r = r0 + m;
        const float* crow = Csm + m * CSTRIDE;

        float s0 = 0.f, s1 = 0.f;
        #pragma unroll
        for (int jj = 0; jj < 8; ++jj) {
            int j = lane + jj * 32;
            float h = gelu_exact(crow[j] + b1c[j]);
            s0 += h * w2c0[j];
            s1 += h * w2c1[j];
        }
        s0 = warp_sum(s0);
        s1 = warp_sum(s1);
        float comp0 = tanhf(s0 + b2_0);
        float comp1 = tanhf(s1 + b2_1);

        // routing (calibration monotone -> argmax of raw scores)
        float cv = -INFINITY; int ci = 1 << 20;
        if (lane < NUM_CL) { cv = crow[COMP_H + lane]; ci = lane; }
        warp_argmax(cv, ci);
        float tv = -INFINITY; int tl = 1 << 20;
        if (lane < TPC) { tv = crow[COMP_H + NUM_CL + ci * TPC + lane]; tl = lane; }
        warp_argmax(tv, tl);
        const int tile = ci * TPC + tl;

        // tiny spline MLP
        float contrib = 0.f;
        if (lane < GRIDW) {
            int g = lane;
            float hw = comp0 * sw1[tile * 32 + g] + comp1 * sw1[tile * 32 + 16 + g]
                       + sb1[tile * 16 + g];
            hw = fmaxf(hw, 0.f);
            contrib = hw * sw2[tile * 16 + g];
        }
        float mag = warp_sum(contrib) + sb2[tile];
        const float factor = mag * oscale;

        // residual + layernorm (fp32 exact, float4 vectorized, register-cached)
        const float4* xr4 = (const float4*)(X + (size_t)r * D_MODEL);
        const float4* dr4 = (const float4*)(dirs + (size_t)tile * D_MODEL);
        const float4* g4  = (const float4*)gamma;
        const float4* be4 = (const float4*)beta;
        float4* o4 = (float4*)(out + (size_t)r * D_MODEL);
        float4 f4[8];
        float sum = 0.f, sumsq = 0.f;
        #pragma unroll
        for (int ii = 0; ii < 8; ++ii) {
            int i = lane + ii * 32;
            float4 xv = xr4[i], dv = dr4[i];
            float4 y;
            y.x = xv.x + factor * dv.x;
            y.y = xv.y + factor * dv.y;
            y.z = xv.z + factor * dv.z;
            y.w = xv.w + factor * dv.w;
            f4[ii] = y;
            sum   += y.x + y.y + y.z + y.w;
            sumsq += y.x * y.x + y.y * y.y + y.z * y.z + y.w * y.w;
        }
        sum   = warp_sum(sum);
        sumsq = warp_sum(sumsq);
        const float mu   = sum * (1.f / D_MODEL);
        const float var  = sumsq * (1.f / D_MODEL) - mu * mu;
        const float rstd = rsqrtf(var + EPS_LN);
        #pragma unroll
        for (int ii = 0; ii < 8; ++ii) {
            int i = lane + ii * 32;
            float4 gv = g4[i], bv = be4[i], y = f4[ii], o;
            o.x = (y.x - mu) * rstd * gv.x + bv.x;
            o.y = (y.y - mu) * rstd * gv.y + bv.y;
            o.z = (y.z - mu) * rstd * gv.z + bv.z;
            o.w = (y.w - mu) * rstd * gv.w + bv.w;
            o4[i] = o;
        }
    }
}

// ---------------- launch ----------------
extern "C" void kernel_launch(void* const* d_in, const int* in_sizes, int n_in,
                              void* d_out, int out_size) {
    const float* x      = (const float*)d_in[0];
    const float* sraw   = (const float*)d_in[1];
    // d_in[2] knot_values, d_in[3] temperature: unused (calibration monotone)
    const float* cw1    = (const float*)d_in[4];
    const float* cb1    = (const float*)d_in[5];
    const float* cw2    = (const float*)d_in[6];
    const float* cb2    = (const float*)d_in[7];
    const float* sw1    = (const float*)d_in[8];
    const float* sb1    = (const float*)d_in[9];
    const float* sw2    = (const float*)d_in[10];
    const float* sb2    = (const float*)d_in[11];
    const float* dirs   = (const float*)d_in[12];
    const float* gamma  = (const float*)d_in[13];
    const float* beta   = (const float*)d_in[14];
    const float* oscale = (const float*)d_in[15];
    float* out = (float*)d_out;

    const int N = in_sizes[0] / D_MODEL;     // 16384
    const int nblocks = N / M_BLK;           // 256

    cudaFuncSetAttribute(fused_kernel,
                         cudaFuncAttributeMaxDynamicSharedMemorySize, SMEM_TOTAL);

    prep_kernel<<<384, 256>>>(cw1, sraw);
    fused_kernel<<<nblocks, NTHREADS, SMEM_TOTAL>>>(
        x, cb1, cw2, cb2, sw1, sb1, sw2, sb2, dirs, gamma, beta, oscale, out);
}

// round 16
// speedup vs baseline: 1.3807x; 1.0551x over previous
#include <cuda_runtime.h>
#include <cuda_bf16.h>
#include <cstdint>
#include <math.h>

// ---------------- problem constants ----------------
#define D_MODEL   1024
#define NUM_TILES 64
#define TPC       8
#define NUM_CL    8
#define COMP_H    256
#define GRIDW     16
#define EPS_LN    1e-5f

// ---------------- GEMM config ----------------
#define NCOL_PAD  384              // layout rows (48 n8-tiles); only 328 filled/used
#define NCOL_USE  328              // 256 hidden + 8 cluster + 64 tile
#define M_BLK     64
#define KC        64
#define NCHUNK    (D_MODEL / KC)   // 16
#define ROWB      144              // 128B k-data + 16B pad; ldmatrix conflict-free
#define CSTRIDE   388              // float4-aligned rows, 4-bank row shift
#define NTHREADS  512

#define A_BYTES      (M_BLK * ROWB)           // 9216
#define B_BYTES      (NCOL_PAD * ROWB)        // 55296
#define STAGE_BYTES  (A_BYTES + B_BYTES)      // 64512
#define B_SEGS       (NCOL_USE * 8)           // 2624 16B-segs filled per chunk
#define PARAM_OFF    (2 * STAGE_BYTES)        // 129024 (Csm 99328 aliases stages)
#define SMEM_TOTAL   (PARAM_OFF + 3 * COMP_H * 4)   // 132096

// Wcat, chunk-major: [chunk][row n][k within chunk]
__device__ __nv_bfloat16 g_Wcat[NCHUNK][NCOL_PAD][KC];

// ---------------- fast prep: coalesced packed stores ----------------
// blocks 0..127:  W1 transpose. block b: k-chunk kc=b>>3, n-block nb=b&7 (32 cols).
// blocks 128..145: signature rows. block handles 4 n-rows x full k (1024).
__global__ void __launch_bounds__(256)
prep_kernel(const float* __restrict__ w1,
            const float* __restrict__ raw) {
    const int b = blockIdx.x;
    const int t = threadIdx.x;
    if (b < 128) {
        __shared__ float ts[64][33];
        const int kc = b >> 3, nb = b & 7;
        const int k0 = kc * 64, n0 = nb * 32;
        const float4* w1_4 = (const float4*)w1;
        #pragma unroll
        for (int i = 0; i < 2; ++i) {
            int s = t * 2 + i;                 // 0..511
            int row = s >> 3, q = s & 7;       // row: k-local, q: float4 within 32 cols
            float4 v = w1_4[(size_t)(k0 + row) * (COMP_H / 4) + nb * 8 + q];
            ts[row][q * 4 + 0] = v.x;
            ts[row][q * 4 + 1] = v.y;
            ts[row][q * 4 + 2] = v.z;
            ts[row][q * 4 + 3] = v.w;
        }
        __syncthreads();
        const int nn = t >> 3, seg = t & 7;    // output n-col, 16B k-segment
        uint32_t pk[4];
        #pragma unroll
        for (int j = 0; j < 4; ++j) {
            float a = ts[seg * 8 + 2 * j][nn];
            float c = ts[seg * 8 + 2 * j + 1][nn];
            __nv_bfloat162 p = __floats2bfloat162_rn(a, c);
            pk[j] = *reinterpret_cast<uint32_t*>(&p);
        }
        *(uint4*)&g_Wcat[kc][n0 + nn][seg * 8] = make_uint4(pk[0], pk[1], pk[2], pk[3]);
    } else {
        const int nbase = COMP_H + (b - 128) * 4;      // 256..324
        const int n = nbase + (t >> 6);                // 4 rows per block
        const int kseg = t & 63;                       // 16B segment over k=0..1023
        const int k0 = kseg * 8;
        float v[8];
        if (n < COMP_H + NUM_CL) {
            const int c = n - COMP_H;
            #pragma unroll
            for (int e = 0; e < 8; ++e) v[e] = 0.f;
            #pragma unroll
            for (int j = 0; j < TPC; ++j) {
                const float4* rp = (const float4*)(raw + (size_t)(c * TPC + j) * D_MODEL + k0);
                float4 r0 = rp[0], r1 = rp[1];
                float rr[8] = {r0.x, r0.y, r0.z, r0.w, r1.x, r1.y, r1.z, r1.w};
                #pragma unroll
                for (int e = 0; e < 8; ++e)
                    v[e] += (rr[e] > 0.3f) ? 1.f : ((rr[e] < -0.3f) ? -1.f : 0.f);
            }
            #pragma unroll
            for (int e = 0; e < 8; ++e)
                v[e] = (v[e] > 0.f) ? 1.f : ((v[e] < 0.f) ? -1.f : 0.f);
        } else {
            const float4* rp = (const float4*)(raw + (size_t)(n - COMP_H - NUM_CL) * D_MODEL + k0);
            float4 r0 = rp[0], r1 = rp[1];
            float rr[8] = {r0.x, r0.y, r0.z, r0.w, r1.x, r1.y, r1.z, r1.w};
            #pragma unroll
            for (int e = 0; e < 8; ++e)
                v[e] = (rr[e] > 0.3f) ? 1.f : ((rr[e] < -0.3f) ? -1.f : 0.f);
        }
        uint32_t pk[4];
        #pragma unroll
        for (int j = 0; j < 4; ++j) {
            __nv_bfloat162 p = __floats2bfloat162_rn(v[2 * j], v[2 * j + 1]);
            pk[j] = *reinterpret_cast<uint32_t*>(&p);
        }
        const int chunk = k0 >> 6, kin = k0 & 63;
        *(uint4*)&g_Wcat[chunk][n][kin] = make_uint4(pk[0], pk[1], pk[2], pk[3]);
    }
}

// ---------------- helpers ----------------
__device__ __forceinline__ float gelu_exact(float v) {
    return 0.5f * v * (1.0f + erff(v * 0.7071067811865476f));
}
__device__ __forceinline__ void mma16816(float c[4], const uint32_t a[4],
                                         uint32_t b0, uint32_t b1) {
    asm volatile(
        "mma.sync.aligned.m16n8k16.row.col.f32.bf16.bf16.f32 "
        "{%0,%1,%2,%3}, {%4,%5,%6,%7}, {%8,%9}, {%0,%1,%2,%3};\n"
        : "+f"(c[0]), "+f"(c[1]), "+f"(c[2]), "+f"(c[3])
        : "r"(a[0]), "r"(a[1]), "r"(a[2]), "r"(a[3]), "r"(b0), "r"(b1));
}
__device__ __forceinline__ void ldsm_x4(uint32_t* r, uint32_t addr) {
    asm volatile("ldmatrix.sync.aligned.m8n8.x4.shared.b16 {%0,%1,%2,%3}, [%4];"
                 : "=r"(r[0]), "=r"(r[1]), "=r"(r[2]), "=r"(r[3]) : "r"(addr));
}
__device__ __forceinline__ void cp16(uint32_t dst, const void* src) {
    asm volatile("cp.async.ca.shared.global [%0], [%1], 16;\n" :: "r"(dst), "l"(src));
}
__device__ __forceinline__ void warp_argmax(float& v, int& i) {
    #pragma unroll
    for (int o = 16; o; o >>= 1) {
        float ov = __shfl_xor_sync(0xffffffffu, v, o);
        int   oi = __shfl_xor_sync(0xffffffffu, i, o);
        if (ov > v || (ov == v && oi < i)) { v = ov; i = oi; }
    }
}
__device__ __forceinline__ float warp_sum(float v) {
    #pragma unroll
    for (int o = 16; o; o >>= 1) v += __shfl_xor_sync(0xffffffffu, v, o);
    return v;
}
__device__ __forceinline__ uint32_t as_u32(__nv_bfloat162 h) {
    return *reinterpret_cast<uint32_t*>(&h);
}

// ---------------- main fused kernel ----------------
__global__ void __launch_bounds__(NTHREADS)
fused_kernel(const float* __restrict__ X,
             const float* __restrict__ cb1,
             const float* __restrict__ cw2,
             const float* __restrict__ cb2,
             const float* __restrict__ sw1,
             const float* __restrict__ sb1,
             const float* __restrict__ sw2,
             const float* __restrict__ sb2,
             const float* __restrict__ dirs,
             const float* __restrict__ gamma,
             const float* __restrict__ beta,
             const float* __restrict__ oscale_p,
             float* __restrict__ out) {
    extern __shared__ char sm[];
    float* Csm  = (float*)sm;
    float* b1c  = (float*)(sm + PARAM_OFF);
    float* w2c0 = b1c + COMP_H;
    float* w2c1 = w2c0 + COMP_H;
    const uint32_t smem_u32 = (uint32_t)__cvta_generic_to_shared(sm);

    const int tid  = threadIdx.x;
    const int lane = tid & 31;
    const int wid  = tid >> 5;      // 0..15
    const int mw   = wid & 1;       // 2 m-groups of 32 rows
    const int nw   = wid >> 1;      // 8 n-groups of 48 cols (6 n8-tiles)
    const bool compute = (nw < 7);  // nw=7's 6 tiles are all dead columns
    const int r0   = blockIdx.x * M_BLK;

    if (tid < COMP_H) {
        b1c[tid]  = cb1[tid];
        w2c0[tid] = cw2[tid * 2 + 0];
        w2c1[tid] = cw2[tid * 2 + 1];
    }
    const float oscale = oscale_p[0];
    const float b2_0 = cb2[0];
    const float b2_1 = cb2[1];

    float acc[2][6][4];
    #pragma unroll
    for (int mt = 0; mt < 2; ++mt)
        #pragma unroll
        for (int nt = 0; nt < 6; ++nt)
            #pragma unroll
            for (int j = 0; j < 4; ++j) acc[mt][nt][j] = 0.f;

    const float4* X4 = (const float4*)X;
    const int arow = tid >> 3, asg = tid & 7;      // A-fill: 512 segs of 16B

    // per-warp ldmatrix offsets (within a stage)
    const uint32_t a_lm0 = (uint32_t)((mw * 32 + (lane & 15)) * ROWB + (lane >> 4) * 16);
    const uint32_t a_lm1 = a_lm0 + 16u * ROWB;
    const uint32_t b_lm4 = (uint32_t)((((lane >> 4) & 1) * 8 + (lane & 7)) * ROWB
                                      + ((lane >> 3) & 1) * 16);

    auto fill_B = [&](int kc, int stage) {
        const char* src = (const char*)&g_Wcat[kc][0][0];
        uint32_t bb = smem_u32 + stage * STAGE_BYTES + A_BYTES;
        #pragma unroll
        for (int rep = 0; rep < 6; ++rep) {
            int s = tid + rep * NTHREADS;
            if (s < B_SEGS)                      // only the 328 live rows
                cp16(bb + (s >> 3) * ROWB + (s & 7) * 16, src + s * 16);
        }
        asm volatile("cp.async.commit_group;\n");
    };
    auto store_A = [&](const float4& v0, const float4& v1, int stage) {
        uint4 hh = make_uint4(as_u32(__floats2bfloat162_rn(v0.x, v0.y)),
                              as_u32(__floats2bfloat162_rn(v0.z, v0.w)),
                              as_u32(__floats2bfloat162_rn(v1.x, v1.y)),
                              as_u32(__floats2bfloat162_rn(v1.z, v1.w)));
        *(uint4*)(sm + stage * STAGE_BYTES + arow * ROWB + asg * 16) = hh;
    };

    // ---- prologue: stage 0 <- chunk 0 ----
    {
        fill_B(0, 0);
        const float4* p = X4 + (size_t)(r0 + arow) * (D_MODEL / 4) + asg * 2;
        float4 v0 = p[0], v1 = p[1];
        store_A(v0, v1, 0);
        asm volatile("cp.async.wait_group 0;\n");
        __syncthreads();
    }

    // ---- pipelined mainloop ----
    for (int kc = 0; kc < NCHUNK; ++kc) {
        const int cur = kc & 1, nxt = cur ^ 1;
        const bool has_next = (kc + 1 < NCHUNK);
        const uint32_t sb = smem_u32 + cur * STAGE_BYTES;

        float4 v0, v1;
        if (has_next) {
            const float4* p = X4 + (size_t)(r0 + arow) * (D_MODEL / 4)
                              + (kc + 1) * (KC / 4) + asg * 2;
            v0 = p[0]; v1 = p[1];
            fill_B(kc + 1, nxt);
        }

        // MMA block (live warps only): flat 12-pair LDSM-pipelined stream
        if (compute) {
            const uint32_t bb0 = sb + A_BYTES + (uint32_t)(nw * 48 * ROWB);
            uint32_t A0[4], A1[4], B[2][4];
            ldsm_x4(A0, sb + a_lm0);
            ldsm_x4(A1, sb + a_lm1);
            ldsm_x4(B[0], bb0 + b_lm4);          // pair j=0
            #pragma unroll
            for (int j = 0; j < 12; ++j) {
                const int ks = j / 3, p = j % 3;
                const int curb = j & 1;
                if (j < 11) {
                    const int jn = j + 1;
                    ldsm_x4(B[curb ^ 1],
                            bb0 + (uint32_t)((jn / 3) * 32)
                                + (uint32_t)((jn % 3) * 16 * ROWB) + b_lm4);
                }
                mma16816(acc[0][2 * p],     A0, B[curb][0], B[curb][1]);
                mma16816(acc[1][2 * p],     A1, B[curb][0], B[curb][1]);
                mma16816(acc[0][2 * p + 1], A0, B[curb][2], B[curb][3]);
                mma16816(acc[1][2 * p + 1], A1, B[curb][2], B[curb][3]);
                if (p == 2 && ks < 3) {
                    ldsm_x4(A0, sb + a_lm0 + (ks + 1) * 32);
                    ldsm_x4(A1, sb + a_lm1 + (ks + 1) * 32);
                }
            }
        }

        if (has_next) store_A(v0, v1, nxt);
        asm volatile("cp.async.wait_group 0;\n");
        __syncthreads();
    }

    // ---- dump C to smem (stages dead now; nw=7 writes zeros, unread) ----
    #pragma unroll
    for (int mt = 0; mt < 2; ++mt)
        #pragma unroll
        for (int nt = 0; nt < 6; ++nt) {
            int cr = mw * 32 + mt * 16 + (lane >> 2);
            int cc = (nw * 6 + nt) * 8 + (lane & 3) * 2;
            *(float2*)&Csm[cr * CSTRIDE + cc] =
                make_float2(acc[mt][nt][0], acc[mt][nt][1]);
            *(float2*)&Csm[(cr + 8) * CSTRIDE + cc] =
                make_float2(acc[mt][nt][2], acc[mt][nt][3]);
        }
    __syncthreads();

    // ---- epilogue: one warp per token, 4 tokens per warp ----
    for (int it = 0; it < 4; ++it) {
        const int m = wid * 4 + it;
        const int r = r0 + m;
        const float* crow = Csm + m * CSTRIDE;

        float s0 = 0.f, s1 = 0.f;
        #pragma unroll
        for (int jj = 0; jj < 8; ++jj) {
            int j = lane + jj * 32;
            float h = gelu_exact(crow[j] + b1c[j]);
            s0 += h * w2c0[j];
            s1 += h * w2c1[j];
        }
        s0 = warp_sum(s0);
        s1 = warp_sum(s1);
        float comp0 = tanhf(s0 + b2_0);
        float comp1 = tanhf(s1 + b2_1);

        // routing (calibration monotone -> argmax of raw scores)
        float cv = -INFINITY; int ci = 1 << 20;
        if (lane < NUM_CL) { cv = crow[COMP_H + lane]; ci = lane; }
        warp_argmax(cv, ci);
        float tv = -INFINITY; int tl = 1 << 20;
        if (lane < TPC) { tv = crow[COMP_H + NUM_CL + ci * TPC + lane]; tl = lane; }
        warp_argmax(tv, tl);
        const int tile = ci * TPC + tl;

        // tiny spline MLP
        float contrib = 0.f;
        if (lane < GRIDW) {
            int g = lane;
            float hw = comp0 * sw1[tile * 32 + g] + comp1 * sw1[tile * 32 + 16 + g]
                       + sb1[tile * 16 + g];
            hw = fmaxf(hw, 0.f);
            contrib = hw * sw2[tile * 16 + g];
        }
        float mag = warp_sum(contrib) + sb2[tile];
        const float factor = mag * oscale;

        // residual + layernorm (fp32 exact, float4 vectorized, register-cached)
        const float4* xr4 = (const float4*)(X + (size_t)r * D_MODEL);
        const float4* dr4 = (const float4*)(dirs + (size_t)tile * D_MODEL);
        const float4* g4  = (const float4*)gamma;
        const float4* be4 = (const float4*)beta;
        float4* o4 = (float4*)(out + (size_t)r * D_MODEL);
        float4 f4[8];
        float sum = 0.f, sumsq = 0.f;
        #pragma unroll
        for (int ii = 0; ii < 8; ++ii) {
            int i = lane + ii * 32;
            float4 xv = xr4[i], dv = dr4[i];
            float4 y;
            y.x = xv.x + factor * dv.x;
            y.y = xv.y + factor * dv.y;
            y.z = xv.z + factor * dv.z;
            y.w = xv.w + factor * dv.w;
            f4[ii] = y;
            sum   += y.x + y.y + y.z + y.w;
            sumsq += y.x * y.x + y.y * y.y + y.z * y.z + y.w * y.w;
        }
        sum   = warp_sum(sum);
        sumsq = warp_sum(sumsq);
        const float mu   = sum * (1.f / D_MODEL);
        const float var  = sumsq * (1.f / D_MODEL) - mu * mu;
        const float rstd = rsqrtf(var + EPS_LN);
        #pragma unroll
        for (int ii = 0; ii < 8; ++ii) {
            int i = lane + ii * 32;
            float4 gv = g4[i], bv = be4[i], y = f4[ii], o;
            o.x = (y.x - mu) * rstd * gv.x + bv.x;
            o.y = (y.y - mu) * rstd * gv.y + bv.y;
            o.z = (y.z - mu) * rstd * gv.z + bv.z;
            o.w = (y.w - mu) * rstd * gv.w + bv.w;
            o4[i] = o;
        }
    }
}

// ---------------- launch ----------------
extern "C" void kernel_launch(void* const* d_in, const int* in_sizes, int n_in,
                              void* d_out, int out_size) {
    const float* x      = (const float*)d_in[0];
    const float* sraw   = (const float*)d_in[1];
    // d_in[2] knot_values, d_in[3] temperature: unused (calibration monotone)
    const float* cw1    = (const float*)d_in[4];
    const float* cb1    = (const float*)d_in[5];
    const float* cw2    = (const float*)d_in[6];
    const float* cb2    = (const float*)d_in[7];
    const float* sw1    = (const float*)d_in[8];
    const float* sb1    = (const float*)d_in[9];
    const float* sw2    = (const float*)d_in[10];
    const float* sb2    = (const float*)d_in[11];
    const float* dirs   = (const float*)d_in[12];
    const float* gamma  = (const float*)d_in[13];
    const float* beta   = (const float*)d_in[14];
    const float* oscale = (const float*)d_in[15];
    float* out = (float*)d_out;

    const int N = in_sizes[0] / D_MODEL;     // 16384
    const int nblocks = N / M_BLK;           // 256

    cudaFuncSetAttribute(fused_kernel,
                         cudaFuncAttributeMaxDynamicSharedMemorySize, SMEM_TOTAL);

    prep_kernel<<<128 + 18, 256>>>(cw1, sraw);
    fused_kernel<<<nblocks, NTHREADS, SMEM_TOTAL>>>(
        x, cb1, cw2, cb2, sw1, sb1, sw2, sb2, dirs, gamma, beta, oscale, out);
}

// round 17
// speedup vs baseline: 1.3813x; 1.0004x over previous
#include <cuda_runtime.h>
#include <cuda_bf16.h>
#include <cstdint>
#include <math.h>

// ---------------- problem constants ----------------
#define D_MODEL   1024
#define NUM_TILES 64
#define TPC       8
#define NUM_CL    8
#define COMP_H    256
#define GRIDW     16
#define EPS_LN    1e-5f

// ---------------- GEMM config ----------------
#define NCOL_PAD  384              // layout rows (48 n8-tiles); 336 staged, 328 live
#define NCOL_FILL 336              // staged rows per chunk (42 tiles; rows 328-335 zeros)
#define M_BLK     64
#define KC        64
#define NCHUNK    (D_MODEL / KC)   // 16
#define ROWB      144              // 128B k-data + 16B pad; ldmatrix conflict-free
#define CSTRIDE   388              // float4-aligned rows, 4-bank row shift
#define NTHREADS  512

#define A_BYTES      (M_BLK * ROWB)           // 9216
#define B_BYTES      (NCOL_PAD * ROWB)        // 55296
#define STAGE_BYTES  (A_BYTES + B_BYTES)      // 64512
#define B_SEGS       (NCOL_FILL * 8)          // 2688 16B-segs per chunk
#define PARAM_OFF    (2 * STAGE_BYTES)        // 129024 (Csm 99328 aliases stages)
#define SMEM_TOTAL   (PARAM_OFF + 3 * COMP_H * 4)   // 132096

// Wcat, chunk-major: [chunk][row n][k within chunk]; zero-initialized device global
__device__ __nv_bfloat16 g_Wcat[NCHUNK][NCOL_PAD][KC];

// ---------------- fast prep: coalesced packed stores ----------------
// blocks 0..127:  W1 transpose. block b: k-chunk kc=b>>3, n-block nb=b&7 (32 cols).
// blocks 128..163: signature rows. block handles 2 n-rows x full k (1024).
__global__ void __launch_bounds__(256)
prep_kernel(const float* __restrict__ w1,
            const float* __restrict__ raw) {
    const int b = blockIdx.x;
    const int t = threadIdx.x;
    if (b < 128) {
        __shared__ float ts[64][33];
        const int kc = b >> 3, nb = b & 7;
        const int k0 = kc * 64, n0 = nb * 32;
        const float4* w1_4 = (const float4*)w1;
        #pragma unroll
        for (int i = 0; i < 2; ++i) {
            int s = t * 2 + i;                 // 0..511
            int row = s >> 3, q = s & 7;       // row: k-local, q: float4 within 32 cols
            float4 v = w1_4[(size_t)(k0 + row) * (COMP_H / 4) + nb * 8 + q];
            ts[row][q * 4 + 0] = v.x;
            ts[row][q * 4 + 1] = v.y;
            ts[row][q * 4 + 2] = v.z;
            ts[row][q * 4 + 3] = v.w;
        }
        __syncthreads();
        const int nn = t >> 3, seg = t & 7;    // output n-col, 16B k-segment
        uint32_t pk[4];
        #pragma unroll
        for (int j = 0; j < 4; ++j) {
            float a = ts[seg * 8 + 2 * j][nn];
            float c = ts[seg * 8 + 2 * j + 1][nn];
            __nv_bfloat162 p = __floats2bfloat162_rn(a, c);
            pk[j] = *reinterpret_cast<uint32_t*>(&p);
        }
        *(uint4*)&g_Wcat[kc][n0 + nn][seg * 8] = make_uint4(pk[0], pk[1], pk[2], pk[3]);
    } else {
        // 2 rows per block, 128 threads per row -> kseg covers FULL k=0..1023
        const int n = COMP_H + (b - 128) * 2 + (t >> 7);   // 256..327
        const int kseg = t & 127;                          // 16B segment
        const int k0 = kseg * 8;
        float v[8];
        if (n < COMP_H + NUM_CL) {
            const int c = n - COMP_H;
            #pragma unroll
            for (int e = 0; e < 8; ++e) v[e] = 0.f;
            #pragma unroll
            for (int j = 0; j < TPC; ++j) {
                const float4* rp = (const float4*)(raw + (size_t)(c * TPC + j) * D_MODEL + k0);
                float4 r0 = rp[0], r1 = rp[1];
                float rr[8] = {r0.x, r0.y, r0.z, r0.w, r1.x, r1.y, r1.z, r1.w};
                #pragma unroll
                for (int e = 0; e < 8; ++e)
                    v[e] += (rr[e] > 0.3f) ? 1.f : ((rr[e] < -0.3f) ? -1.f : 0.f);
            }
            #pragma unroll
            for (int e = 0; e < 8; ++e)
                v[e] = (v[e] > 0.f) ? 1.f : ((v[e] < 0.f) ? -1.f : 0.f);
        } else {
            const float4* rp = (const float4*)(raw + (size_t)(n - COMP_H - NUM_CL) * D_MODEL + k0);
            float4 r0 = rp[0], r1 = rp[1];
            float rr[8] = {r0.x, r0.y, r0.z, r0.w, r1.x, r1.y, r1.z, r1.w};
            #pragma unroll
            for (int e = 0; e < 8; ++e)
                v[e] = (rr[e] > 0.3f) ? 1.f : ((rr[e] < -0.3f) ? -1.f : 0.f);
        }
        uint32_t pk[4];
        #pragma unroll
        for (int j = 0; j < 4; ++j) {
            __nv_bfloat162 p = __floats2bfloat162_rn(v[2 * j], v[2 * j + 1]);
            pk[j] = *reinterpret_cast<uint32_t*>(&p);
        }
        const int chunk = k0 >> 6, kin = k0 & 63;
        *(uint4*)&g_Wcat[chunk][n][kin] = make_uint4(pk[0], pk[1], pk[2], pk[3]);
    }
}

// ---------------- helpers ----------------
__device__ __forceinline__ float gelu_exact(float v) {
    return 0.5f * v * (1.0f + erff(v * 0.7071067811865476f));
}
__device__ __forceinline__ void mma16816(float c[4], const uint32_t a[4],
                                         uint32_t b0, uint32_t b1) {
    asm volatile(
        "mma.sync.aligned.m16n8k16.row.col.f32.bf16.bf16.f32 "
        "{%0,%1,%2,%3}, {%4,%5,%6,%7}, {%8,%9}, {%0,%1,%2,%3};\n"
        : "+f"(c[0]), "+f"(c[1]), "+f"(c[2]), "+f"(c[3])
        : "r"(a[0]), "r"(a[1]), "r"(a[2]), "r"(a[3]), "r"(b0), "r"(b1));
}
__device__ __forceinline__ void ldsm_x4(uint32_t* r, uint32_t addr) {
    asm volatile("ldmatrix.sync.aligned.m8n8.x4.shared.b16 {%0,%1,%2,%3}, [%4];"
                 : "=r"(r[0]), "=r"(r[1]), "=r"(r[2]), "=r"(r[3]) : "r"(addr));
}
__device__ __forceinline__ void cp16(uint32_t dst, const void* src) {
    asm volatile("cp.async.ca.shared.global [%0], [%1], 16;\n" :: "r"(dst), "l"(src));
}
__device__ __forceinline__ void warp_argmax(float& v, int& i) {
    #pragma unroll
    for (int o = 16; o; o >>= 1) {
        float ov = __shfl_xor_sync(0xffffffffu, v, o);
        int   oi = __shfl_xor_sync(0xffffffffu, i, o);
        if (ov > v || (ov == v && oi < i)) { v = ov; i = oi; }
    }
}
__device__ __forceinline__ float warp_sum(float v) {
    #pragma unroll
    for (int o = 16; o; o >>= 1) v += __shfl_xor_sync(0xffffffffu, v, o);
    return v;
}
__device__ __forceinline__ uint32_t as_u32(__nv_bfloat162 h) {
    return *reinterpret_cast<uint32_t*>(&h);
}

// ---------------- main fused kernel ----------------
__global__ void __launch_bounds__(NTHREADS)
fused_kernel(const float* __restrict__ X,
             const float* __restrict__ cb1,
             const float* __restrict__ cw2,
             const float* __restrict__ cb2,
             const float* __restrict__ sw1,
             const float* __restrict__ sb1,
             const float* __restrict__ sw2,
             const float* __restrict__ sb2,
             const float* __restrict__ dirs,
             const float* __restrict__ gamma,
             const float* __restrict__ beta,
             const float* __restrict__ oscale_p,
             float* __restrict__ out) {
    extern __shared__ char sm[];
    float* Csm  = (float*)sm;
    float* b1c  = (float*)(sm + PARAM_OFF);
    float* w2c0 = b1c + COMP_H;
    float* w2c1 = w2c0 + COMP_H;
    const uint32_t smem_u32 = (uint32_t)__cvta_generic_to_shared(sm);

    const int tid  = threadIdx.x;
    const int lane = tid & 31;
    const int wid  = tid >> 5;      // 0..15
    const int mw   = wid & 1;       // 2 m-groups of 32 rows
    const int nw   = wid >> 1;      // 8 n-groups of 48 cols (6 n8-tiles)
    const bool compute = (nw < 7);  // nw=7's 6 tiles are all dead columns
    const int r0   = blockIdx.x * M_BLK;

    if (tid < COMP_H) {
        b1c[tid]  = cb1[tid];
        w2c0[tid] = cw2[tid * 2 + 0];
        w2c1[tid] = cw2[tid * 2 + 1];
    }
    const float oscale = oscale_p[0];
    const float b2_0 = cb2[0];
    const float b2_1 = cb2[1];

    float acc[2][6][4];
    #pragma unroll
    for (int mt = 0; mt < 2; ++mt)
        #pragma unroll
        for (int nt = 0; nt < 6; ++nt)
            #pragma unroll
            for (int j = 0; j < 4; ++j) acc[mt][nt][j] = 0.f;

    const float4* X4 = (const float4*)X;
    const int arow = tid >> 3, asg = tid & 7;      // A-fill: 512 segs of 16B

    // per-warp ldmatrix offsets (within a stage)
    const uint32_t a_lm0 = (uint32_t)((mw * 32 + (lane & 15)) * ROWB + (lane >> 4) * 16);
    const uint32_t a_lm1 = a_lm0 + 16u * ROWB;
    const uint32_t b_lm4 = (uint32_t)((((lane >> 4) & 1) * 8 + (lane & 7)) * ROWB
                                      + ((lane >> 3) & 1) * 16);

    auto fill_B = [&](int kc, int stage) {
        const char* src = (const char*)&g_Wcat[kc][0][0];
        uint32_t bb = smem_u32 + stage * STAGE_BYTES + A_BYTES;
        #pragma unroll
        for (int rep = 0; rep < 6; ++rep) {
            int s = tid + rep * NTHREADS;
            if (s < B_SEGS)                      // 336 rows (328 live + 8 zero)
                cp16(bb + (s >> 3) * ROWB + (s & 7) * 16, src + s * 16);
        }
        asm volatile("cp.async.commit_group;\n");
    };
    auto store_A = [&](const float4& v0, const float4& v1, int stage) {
        uint4 hh = make_uint4(as_u32(__floats2bfloat162_rn(v0.x, v0.y)),
                              as_u32(__floats2bfloat162_rn(v0.z, v0.w)),
                              as_u32(__floats2bfloat162_rn(v1.x, v1.y)),
                              as_u32(__floats2bfloat162_rn(v1.z, v1.w)));
        *(uint4*)(sm + stage * STAGE_BYTES + arow * ROWB + asg * 16) = hh;
    };

    // ---- prologue: stage 0 <- chunk 0 ----
    {
        fill_B(0, 0);
        const float4* p = X4 + (size_t)(r0 + arow) * (D_MODEL / 4) + asg * 2;
        float4 v0 = p[0], v1 = p[1];
        store_A(v0, v1, 0);
        asm volatile("cp.async.wait_group 0;\n");
        __syncthreads();
    }

    // ---- pipelined mainloop ----
    for (int kc = 0; kc < NCHUNK; ++kc) {
        const int cur = kc & 1, nxt = cur ^ 1;
        const bool has_next = (kc + 1 < NCHUNK);
        const uint32_t sb = smem_u32 + cur * STAGE_BYTES;

        float4 v0, v1;
        if (has_next) {
            const float4* p = X4 + (size_t)(r0 + arow) * (D_MODEL / 4)
                              + (kc + 1) * (KC / 4) + asg * 2;
            v0 = p[0]; v1 = p[1];
            fill_B(kc + 1, nxt);
        }

        // MMA block (live warps only): flat 12-pair LDSM-pipelined stream
        if (compute) {
            const uint32_t bb0 = sb + A_BYTES + (uint32_t)(nw * 48 * ROWB);
            uint32_t A0[4], A1[4], B[2][4];
            ldsm_x4(A0, sb + a_lm0);
            ldsm_x4(A1, sb + a_lm1);
            ldsm_x4(B[0], bb0 + b_lm4);          // pair j=0
            #pragma unroll
            for (int j = 0; j < 12; ++j) {
                const int ks = j / 3, p = j % 3;
                const int curb = j & 1;
                if (j < 11) {
                    const int jn = j + 1;
                    ldsm_x4(B[curb ^ 1],
                            bb0 + (uint32_t)((jn / 3) * 32)
                                + (uint32_t)((jn % 3) * 16 * ROWB) + b_lm4);
                }
                mma16816(acc[0][2 * p],     A0, B[curb][0], B[curb][1]);
                mma16816(acc[1][2 * p],     A1, B[curb][0], B[curb][1]);
                mma16816(acc[0][2 * p + 1], A0, B[curb][2], B[curb][3]);
                mma16816(acc[1][2 * p + 1], A1, B[curb][2], B[curb][3]);
                if (p == 2 && ks < 3) {
                    ldsm_x4(A0, sb + a_lm0 + (ks + 1) * 32);
                    ldsm_x4(A1, sb + a_lm1 + (ks + 1) * 32);
                }
            }
        }

        if (has_next) store_A(v0, v1, nxt);
        asm volatile("cp.async.wait_group 0;\n");
        __syncthreads();
    }

    // ---- dump C to smem (stages dead now; nw=7 writes zeros, unread) ----
    #pragma unroll
    for (int mt = 0; mt < 2; ++mt)
        #pragma unroll
        for (int nt = 0; nt < 6; ++nt) {
            int cr = mw * 32 + mt * 16 + (lane >> 2);
            int cc = (nw * 6 + nt) * 8 + (lane & 3) * 2;
            *(float2*)&Csm[cr * CSTRIDE + cc] =
                make_float2(acc[mt][nt][0], acc[mt][nt][1]);
            *(float2*)&Csm[(cr + 8) * CSTRIDE + cc] =
                make_float2(acc[mt][nt][2], acc[mt][nt][3]);
        }
    __syncthreads();

    // ---- epilogue: one warp per token, 4 tokens per warp ----
    for (int it = 0; it < 4; ++it) {
        const int m = wid * 4 + it;
        const int r = r0 + m;
        const float* crow = Csm + m * CSTRIDE;

        float s0 = 0.f, s1 = 0.f;
        #pragma unroll
        for (int jj = 0; jj < 8; ++jj) {
            int j = lane + jj * 32;
            float h = gelu_exact(crow[j] + b1c[j]);
            s0 += h * w2c0[j];
            s1 += h * w2c1[j];
        }
        s0 = warp_sum(s0);
        s1 = warp_sum(s1);
        float comp0 = tanhf(s0 + b2_0);
        float comp1 = tanhf(s1 + b2_1);

        // routing (calibration monotone -> argmax of raw scores)
        float cv = -INFINITY; int ci = 1 << 20;
        if (lane < NUM_CL) { cv = crow[COMP_H + lane]; ci = lane; }
        warp_argmax(cv, ci);
        float tv = -INFINITY; int tl = 1 << 20;
        if (lane < TPC) { tv = crow[COMP_H + NUM_CL + ci * TPC + lane]; tl = lane; }
        warp_argmax(tv, tl);
        const int tile = ci * TPC + tl;

        // tiny spline MLP
        float contrib = 0.f;
        if (lane < GRIDW) {
            int g = lane;
            float hw = comp0 * sw1[tile * 32 + g] + comp1 * sw1[tile * 32 + 16 + g]
                       + sb1[tile * 16 + g];
            hw = fmaxf(hw, 0.f);
            contrib = hw * sw2[tile * 16 + g];
        }
        float mag = warp_sum(contrib) + sb2[tile];
        const float factor = mag * oscale;

        // residual + layernorm (fp32 exact, float4 vectorized, register-cached)
        const float4* xr4 = (const float4*)(X + (size_t)r * D_MODEL);
        const float4* dr4 = (const float4*)(dirs + (size_t)tile * D_MODEL);
        const float4* g4  = (const float4*)gamma;
        const float4* be4 = (const float4*)beta;
        float4* o4 = (float4*)(out + (size_t)r * D_MODEL);
        float4 f4[8];
        float sum = 0.f, sumsq = 0.f;
        #pragma unroll
        for (int ii = 0; ii < 8; ++ii) {
            int i = lane + ii * 32;
            float4 xv = xr4[i], dv = dr4[i];
            float4 y;
            y.x = xv.x + factor * dv.x;
            y.y = xv.y + factor * dv.y;
            y.z = xv.z + factor * dv.z;
            y.w = xv.w + factor * dv.w;
            f4[ii] = y;
            sum   += y.x + y.y + y.z + y.w;
            sumsq += y.x * y.x + y.y * y.y + y.z * y.z + y.w * y.w;
        }
        sum   = warp_sum(sum);
        sumsq = warp_sum(sumsq);
        const float mu   = sum * (1.f / D_MODEL);
        const float var  = sumsq * (1.f / D_MODEL) - mu * mu;
        const float rstd = rsqrtf(var + EPS_LN);
        #pragma unroll
        for (int ii = 0; ii < 8; ++ii) {
            int i = lane + ii * 32;
            float4 gv = g4[i], bv = be4[i], y = f4[ii], o;
            o.x = (y.x - mu) * rstd * gv.x + bv.x;
            o.y = (y.y - mu) * rstd * gv.y + bv.y;
            o.z = (y.z - mu) * rstd * gv.z + bv.z;
            o.w = (y.w - mu) * rstd * gv.w + bv.w;
            o4[i] = o;
        }
    }
}

// ---------------- launch ----------------
extern "C" void kernel_launch(void* const* d_in, const int* in_sizes, int n_in,
                              void* d_out, int out_size) {
    const float* x      = (const float*)d_in[0];
    const float* sraw   = (const float*)d_in[1];
    // d_in[2] knot_values, d_in[3] temperature: unused (calibration monotone)
    const float* cw1    = (const float*)d_in[4];
    const float* cb1    = (const float*)d_in[5];
    const float* cw2    = (const float*)d_in[6];
    const float* cb2    = (const float*)d_in[7];
    const float* sw1    = (const float*)d_in[8];
    const float* sb1    = (const float*)d_in[9];
    const float* sw2    = (const float*)d_in[10];
    const float* sb2    = (const float*)d_in[11];
    const float* dirs   = (const float*)d_in[12];
    const float* gamma  = (const float*)d_in[13];
    const float* beta   = (const float*)d_in[14];
    const float* oscale = (const float*)d_in[15];
    float* out = (float*)d_out;

    const int N = in_sizes[0] / D_MODEL;     // 16384
    const int nblocks = N / M_BLK;           // 256

    cudaFuncSetAttribute(fused_kernel,
                         cudaFuncAttributeMaxDynamicSharedMemorySize, SMEM_TOTAL);

    prep_kernel<<<128 + 36, 256>>>(cw1, sraw);
    fused_kernel<<<nblocks, NTHREADS, SMEM_TOTAL>>>(
        x, cb1, cw2, cb2, sw1, sb1, sw2, sb2, dirs, gamma, beta, oscale, out);
}